// round 11
// baseline (speedup 1.0000x reference)
#include <cuda_runtime.h>
#include <cfloat>

#define B   32
#define C   512
#define H   56
#define W   56
#define HW  (H * W)          // 3136
#define HW4 (HW / 4)         // 784
#define KD  768
#define NTOT ((size_t)B * C * HW)

#define NGROUP 4
#define GB     (B / NGROUP)  // 8 batches per group

// pooling block geometry (R6-proven): 16 hw4-cols x 16 channel-chunks
#define PTX 16
#define PTY 16
#define PCC (C / PTY)        // 32 channels per thread
#define PBLK_PER_B (HW4 / PTX)   // 49

// conv tiling
#define CROWS 4
#define CTH   (CROWS + 6)
#define CTW   64

// Scratch (alloc-free rule: __device__ globals)
__device__ float g_pooled[B * 2 * HW];
__device__ float g_scale[B * HW];

// ---------------------------------------------------------------------------
// Streams/events: created once at program load (host-side resources, before
// the harness's device-memory checkpoints). The captured graph is identical
// on every call.
// ---------------------------------------------------------------------------
struct PipeRes {
    cudaStream_t s1;
    cudaEvent_t  ev_fork;
    cudaEvent_t  ev_join;
    cudaEvent_t  ev_pool[NGROUP];
    PipeRes() {
        cudaFree(0);  // ensure context
        cudaStreamCreateWithFlags(&s1, cudaStreamNonBlocking);
        cudaEventCreateWithFlags(&ev_fork, cudaEventDisableTiming);
        cudaEventCreateWithFlags(&ev_join, cudaEventDisableTiming);
        for (int i = 0; i < NGROUP; ++i)
            cudaEventCreateWithFlags(&ev_pool[i], cudaEventDisableTiming);
    }
};
static PipeRes g_res;

// ---------------------------------------------------------------------------
// Kernel 1: fused channel max+mean pooling for one batch group (R6 geometry).
// ---------------------------------------------------------------------------
__global__ void __launch_bounds__(PTX * PTY)
pool_kernel(const float4* __restrict__ x4, int b0) {
    int tx = threadIdx.x & (PTX - 1);
    int ty = threadIdx.x >> 4;
    int b   = b0 + blockIdx.y;
    int hw4 = blockIdx.x * PTX + tx;

    const float4* p = x4 + (size_t)b * C * HW4
                         + (size_t)ty * PCC * HW4 + hw4;
    float4 v0 = __ldg(p);
    float4 mx = v0;
    float4 sm = v0;
#pragma unroll
    for (int c = 1; c < PCC; ++c) {
        float4 v = __ldg(p + (size_t)c * HW4);
        mx.x = fmaxf(mx.x, v.x); mx.y = fmaxf(mx.y, v.y);
        mx.z = fmaxf(mx.z, v.z); mx.w = fmaxf(mx.w, v.w);
        sm.x += v.x; sm.y += v.y; sm.z += v.z; sm.w += v.w;
    }

    __shared__ float4 smax[PTY][PTX];
    __shared__ float4 ssum[PTY][PTX];
    smax[ty][tx] = mx;
    ssum[ty][tx] = sm;
    __syncthreads();

#pragma unroll
    for (int s = PTY / 2; s > 0; s >>= 1) {
        if (ty < s) {
            float4 m = smax[ty + s][tx];
            float4 q = ssum[ty + s][tx];
            mx.x = fmaxf(mx.x, m.x); mx.y = fmaxf(mx.y, m.y);
            mx.z = fmaxf(mx.z, m.z); mx.w = fmaxf(mx.w, m.w);
            sm.x += q.x; sm.y += q.y; sm.z += q.z; sm.w += q.w;
            smax[ty][tx] = mx;
            ssum[ty][tx] = sm;
        }
        __syncthreads();
    }

    if (ty == 0) {
        const float inv = 1.0f / C;
        sm.x *= inv; sm.y *= inv; sm.z *= inv; sm.w *= inv;
        float4* pool4 = reinterpret_cast<float4*>(g_pooled);
        pool4[(b * 2 * HW) / 4 + hw4]      = mx;
        pool4[(b * 2 * HW + HW) / 4 + hw4] = sm;
    }
}

// ---------------------------------------------------------------------------
// Kernel 2: smem-tiled 7x7 conv + sigmoid + keyword bias for one group.
// ---------------------------------------------------------------------------
__global__ void conv_kernel(const float* __restrict__ conv_w,
                            const float* __restrict__ conv_b,
                            const float* __restrict__ keyword,
                            const float* __restrict__ proj_w,
                            const float* __restrict__ proj_b, int b0) {
    __shared__ float tile[2][CTH][CTW];
    __shared__ float wts[98];
    __shared__ float wsum[8];
    __shared__ float sbias;

    int b  = b0 + blockIdx.y;
    int r0 = blockIdx.x * CROWS;
    int tid = threadIdx.x;

    if (tid < 98) wts[tid] = conv_w[tid];

    {
        float s = 0.0f;
        const float* kb = keyword + b * KD;
#pragma unroll
        for (int k = tid; k < KD; k += 256)
            s += kb[k] * proj_w[k];
#pragma unroll
        for (int off = 16; off > 0; off >>= 1)
            s += __shfl_down_sync(0xFFFFFFFFu, s, off);
        if ((tid & 31) == 0) wsum[tid >> 5] = s;
    }

    const float* pb = g_pooled + b * 2 * HW;
    for (int i = tid; i < 2 * CTH * CTW; i += 256) {
        int ci = i / (CTH * CTW);
        int rr = (i / CTW) % CTH;
        int cc = i % CTW;
        int hh = r0 + rr - 3;
        int ww = cc - 3;
        float v = 0.0f;
        if ((unsigned)hh < (unsigned)H && (unsigned)ww < (unsigned)W)
            v = pb[ci * HW + hh * W + ww];
        tile[ci][rr][cc] = v;
    }
    __syncthreads();

    if (tid == 0) {
        float t = 0.0f;
#pragma unroll
        for (int i = 0; i < 8; ++i) t += wsum[i];
        sbias = t + proj_b[0] + conv_b[0];
    }
    __syncthreads();

    if (tid < CROWS * W) {
        int r = tid / W;
        int w = tid - r * W;
        float acc = sbias;
#pragma unroll
        for (int ci = 0; ci < 2; ++ci) {
#pragma unroll
            for (int kh = 0; kh < 7; ++kh) {
#pragma unroll
                for (int kw = 0; kw < 7; ++kw) {
                    acc += tile[ci][r + kh][w + kw] * wts[ci * 49 + kh * 7 + kw];
                }
            }
        }
        g_scale[b * HW + (r0 + r) * W + w] = 1.0f / (1.0f + __expf(-acc));
    }
}

// ---------------------------------------------------------------------------
// Kernel 3: out = x * scale for one batch group.
// ---------------------------------------------------------------------------
__global__ void mul_kernel(const float4* __restrict__ x4,
                           float4* __restrict__ out4, int b0) {
    const int CHW4 = C * HW4;
    const int NG4  = GB * CHW4;
    int i = blockIdx.x * blockDim.x + threadIdx.x;
    if (i >= NG4) return;
    int bl  = i / CHW4;
    int rem = i - bl * CHW4;
    int hw4 = rem % HW4;
    int b   = b0 + bl;

    size_t gi = (size_t)b * CHW4 + rem;
    float4 s = reinterpret_cast<const float4*>(g_scale)[b * HW4 + hw4];
    float4 v = __ldcs(x4 + gi);
    v.x *= s.x; v.y *= s.y; v.z *= s.z; v.w *= s.w;
    __stcs(out4 + gi, v);
}

// ---------------------------------------------------------------------------
extern "C" void kernel_launch(void* const* d_in, const int* in_sizes, int n_in,
                              void* d_out, int out_size) {
    const float* x       = (const float*)d_in[0];
    const float* keyword = (const float*)d_in[1];
    const float* conv_w  = (const float*)d_in[2];
    const float* conv_b  = (const float*)d_in[3];
    const float* proj_w  = (const float*)d_in[4];
    const float* proj_b  = (const float*)d_in[5];
    float* out = (float*)d_out;

    cudaStream_t s1 = g_res.s1;

    // fork side stream into the captured graph
    cudaEventRecord(g_res.ev_fork, 0);
    cudaStreamWaitEvent(s1, g_res.ev_fork, 0);

    const int NG4 = GB * C * HW4;
    for (int g = 0; g < NGROUP; ++g) {
        int b0 = g * GB;
        // producer: pool on capture stream
        {
            dim3 grid(PBLK_PER_B, GB);       // 49 x 8
            pool_kernel<<<grid, PTX * PTY, 0, 0>>>((const float4*)x, b0);
        }
        cudaEventRecord(g_res.ev_pool[g], 0);
        cudaStreamWaitEvent(s1, g_res.ev_pool[g], 0);
        // consumers: conv + mul on side stream (overlap next group's pool)
        {
            dim3 grid(H / CROWS, GB);        // 14 x 8
            conv_kernel<<<grid, 256, 0, s1>>>(conv_w, conv_b, keyword,
                                              proj_w, proj_b, b0);
        }
        mul_kernel<<<(NG4 + 255) / 256, 256, 0, s1>>>(
            (const float4*)x, (float4*)out, b0);
    }

    // join side stream back into the capture stream
    cudaEventRecord(g_res.ev_join, s1);
    cudaStreamWaitEvent(0, g_res.ev_join, 0);
}

// round 12
// speedup vs baseline: 1.0333x; 1.0333x over previous
#include <cuda_runtime.h>
#include <cfloat>

#define B   32
#define C   512
#define H   56
#define W   56
#define HW  (H * W)          // 3136
#define HW4 (HW / 4)         // 784
#define KD  768
#define NTOT ((size_t)B * C * HW)

// pooling block geometry (R6-proven): 16 hw4-cols x 16 channel-chunks
#define PTX 16
#define PTY 16
#define PCC (C / PTY)        // 32 channels per thread
#define PBLK_PER_B (HW4 / PTX)   // 49

// conv tiling: 8 output rows per block
#define CROWS 8
#define CTH   (CROWS + 6)    // 14
#define CTW   64

// Scratch (alloc-free rule: __device__ globals)
__device__ float g_pooled[B * 2 * HW];
__device__ float g_scale[B * HW];

// ---------------------------------------------------------------------------
// Kernel 1: fused channel max+mean pooling (R6-proven geometry, untouched).
// ---------------------------------------------------------------------------
__global__ void __launch_bounds__(PTX * PTY)
pool_kernel(const float4* __restrict__ x4) {
    int tx = threadIdx.x & (PTX - 1);
    int ty = threadIdx.x >> 4;
    int b   = blockIdx.y;
    int hw4 = blockIdx.x * PTX + tx;

    const float4* p = x4 + (size_t)b * C * HW4
                         + (size_t)ty * PCC * HW4 + hw4;
    float4 v0 = __ldg(p);
    float4 mx = v0;
    float4 sm = v0;
#pragma unroll
    for (int c = 1; c < PCC; ++c) {
        float4 v = __ldg(p + (size_t)c * HW4);
        mx.x = fmaxf(mx.x, v.x); mx.y = fmaxf(mx.y, v.y);
        mx.z = fmaxf(mx.z, v.z); mx.w = fmaxf(mx.w, v.w);
        sm.x += v.x; sm.y += v.y; sm.z += v.z; sm.w += v.w;
    }

    __shared__ float4 smax[PTY][PTX];
    __shared__ float4 ssum[PTY][PTX];
    smax[ty][tx] = mx;
    ssum[ty][tx] = sm;
    __syncthreads();

#pragma unroll
    for (int s = PTY / 2; s > 0; s >>= 1) {
        if (ty < s) {
            float4 m = smax[ty + s][tx];
            float4 q = ssum[ty + s][tx];
            mx.x = fmaxf(mx.x, m.x); mx.y = fmaxf(mx.y, m.y);
            mx.z = fmaxf(mx.z, m.z); mx.w = fmaxf(mx.w, m.w);
            sm.x += q.x; sm.y += q.y; sm.z += q.z; sm.w += q.w;
            smax[ty][tx] = mx;
            ssum[ty][tx] = sm;
        }
        __syncthreads();
    }

    if (ty == 0) {
        const float inv = 1.0f / C;
        sm.x *= inv; sm.y *= inv; sm.z *= inv; sm.w *= inv;
        float4* pool4 = reinterpret_cast<float4*>(g_pooled);
        pool4[(b * 2 * HW) / 4 + hw4]      = mx;
        pool4[(b * 2 * HW + HW) / 4 + hw4] = sm;
    }
}

// ---------------------------------------------------------------------------
// Kernel 2: smem-tiled 7x7 conv + sigmoid + keyword bias.
// CROWS=8: 224 blocks, 448 outputs per block (2 per thread), 7 KB tile.
// ---------------------------------------------------------------------------
__global__ void conv_kernel(const float* __restrict__ conv_w,
                            const float* __restrict__ conv_b,
                            const float* __restrict__ keyword,
                            const float* __restrict__ proj_w,
                            const float* __restrict__ proj_b) {
    __shared__ float tile[2][CTH][CTW];   // 7 KB
    __shared__ float wts[98];
    __shared__ float wsum[8];
    __shared__ float sbias;

    int b  = blockIdx.y;
    int r0 = blockIdx.x * CROWS;
    int tid = threadIdx.x;

    if (tid < 98) wts[tid] = __ldg(conv_w + tid);

    // keyword bias dot
    {
        float s = 0.0f;
        const float* kb = keyword + b * KD;
#pragma unroll
        for (int k = tid; k < KD; k += 256)
            s += __ldg(kb + k) * __ldg(proj_w + k);
#pragma unroll
        for (int off = 16; off > 0; off >>= 1)
            s += __shfl_down_sync(0xFFFFFFFFu, s, off);
        if ((tid & 31) == 0) wsum[tid >> 5] = s;
    }

    // cooperative pooled-tile load (2 x 14 x 64, zero-padded halo)
    const float* pb = g_pooled + b * 2 * HW;
    for (int i = tid; i < 2 * CTH * CTW; i += 256) {
        int ci = i / (CTH * CTW);
        int rr = (i / CTW) % CTH;
        int cc = i % CTW;
        int hh = r0 + rr - 3;
        int ww = cc - 3;
        float v = 0.0f;
        if ((unsigned)hh < (unsigned)H && (unsigned)ww < (unsigned)W)
            v = pb[ci * HW + hh * W + ww];
        tile[ci][rr][cc] = v;
    }
    __syncthreads();

    if (tid == 0) {
        float t = 0.0f;
#pragma unroll
        for (int i = 0; i < 8; ++i) t += wsum[i];
        sbias = t + __ldg(proj_b) + __ldg(conv_b);
    }
    __syncthreads();

    // 448 outputs over 256 threads (2 per thread)
#pragma unroll
    for (int o = tid; o < CROWS * W; o += 256) {
        int r = o / W;
        int w = o - r * W;
        float acc = sbias;
#pragma unroll
        for (int ci = 0; ci < 2; ++ci) {
#pragma unroll
            for (int kh = 0; kh < 7; ++kh) {
#pragma unroll
                for (int kw = 0; kw < 7; ++kw) {
                    acc += tile[ci][r + kh][w + kw] * wts[ci * 49 + kh * 7 + kw];
                }
            }
        }
        g_scale[b * HW + (r0 + r) * W + w] = 1.0f / (1.0f + __expf(-acc));
    }
}

// ---------------------------------------------------------------------------
// Kernel 3: out = x * scale, REVERSED block order so the first-processed
// addresses are the tail of x that pool left L2-resident.
// ---------------------------------------------------------------------------
__global__ void mul_kernel(const float4* __restrict__ x4,
                           float4* __restrict__ out4) {
    const int CHW4 = C * HW4;
    int blk = gridDim.x - 1 - blockIdx.x;         // reverse order
    int i = blk * blockDim.x + threadIdx.x;
    if (i >= (int)(NTOT / 4)) return;
    int b   = i / CHW4;
    int rem = i - b * CHW4;
    int hw4 = rem % HW4;

    float4 s = reinterpret_cast<const float4*>(g_scale)[b * HW4 + hw4];
    float4 v = __ldcs(x4 + i);
    v.x *= s.x; v.y *= s.y; v.z *= s.z; v.w *= s.w;
    __stcs(out4 + i, v);
}

// ---------------------------------------------------------------------------
extern "C" void kernel_launch(void* const* d_in, const int* in_sizes, int n_in,
                              void* d_out, int out_size) {
    const float* x       = (const float*)d_in[0];
    const float* keyword = (const float*)d_in[1];
    const float* conv_w  = (const float*)d_in[2];
    const float* conv_b  = (const float*)d_in[3];
    const float* proj_w  = (const float*)d_in[4];
    const float* proj_b  = (const float*)d_in[5];
    float* out = (float*)d_out;

    {
        dim3 grid(PBLK_PER_B, B);        // 49 x 32
        pool_kernel<<<grid, PTX * PTY>>>((const float4*)x);
    }
    {
        dim3 grid(H / CROWS, B);         // 7 x 32 = 224
        conv_kernel<<<grid, 256>>>(conv_w, conv_b, keyword, proj_w, proj_b);
    }
    {
        int n4 = (int)(NTOT / 4);
        mul_kernel<<<(n4 + 255) / 256, 256>>>((const float4*)x, (float4*)out);
    }
}

// round 13
// speedup vs baseline: 1.0352x; 1.0018x over previous
#include <cuda_runtime.h>
#include <cfloat>

#define B   32
#define C   512
#define H   56
#define W   56
#define HW  (H * W)          // 3136
#define HW4 (HW / 4)         // 784
#define KD  768
#define NTOT ((size_t)B * C * HW)

// pooling block geometry (R6-proven): 16 hw4-cols x 16 channel-chunks
#define PTX 16
#define PTY 16
#define PCC (C / PTY)        // 32 channels per thread
#define PBLK_PER_B (HW4 / PTX)   // 49

// conv tiling: 8 output rows per block
#define CROWS 8
#define CTH   (CROWS + 6)    // 14
#define CTW   64

// Scratch (alloc-free rule: __device__ globals)
__device__ float g_pooled[B * 2 * HW];
__device__ float g_scale[B * HW];

// ---------------------------------------------------------------------------
// Kernel 1: fused channel max+mean pooling (R6-proven geometry, untouched).
// ---------------------------------------------------------------------------
__global__ void __launch_bounds__(PTX * PTY)
pool_kernel(const float4* __restrict__ x4) {
    int tx = threadIdx.x & (PTX - 1);
    int ty = threadIdx.x >> 4;
    int b   = blockIdx.y;
    int hw4 = blockIdx.x * PTX + tx;

    const float4* p = x4 + (size_t)b * C * HW4
                         + (size_t)ty * PCC * HW4 + hw4;
    float4 v0 = __ldg(p);
    float4 mx = v0;
    float4 sm = v0;
#pragma unroll
    for (int c = 1; c < PCC; ++c) {
        float4 v = __ldg(p + (size_t)c * HW4);
        mx.x = fmaxf(mx.x, v.x); mx.y = fmaxf(mx.y, v.y);
        mx.z = fmaxf(mx.z, v.z); mx.w = fmaxf(mx.w, v.w);
        sm.x += v.x; sm.y += v.y; sm.z += v.z; sm.w += v.w;
    }

    __shared__ float4 smax[PTY][PTX];
    __shared__ float4 ssum[PTY][PTX];
    smax[ty][tx] = mx;
    ssum[ty][tx] = sm;
    __syncthreads();

#pragma unroll
    for (int s = PTY / 2; s > 0; s >>= 1) {
        if (ty < s) {
            float4 m = smax[ty + s][tx];
            float4 q = ssum[ty + s][tx];
            mx.x = fmaxf(mx.x, m.x); mx.y = fmaxf(mx.y, m.y);
            mx.z = fmaxf(mx.z, m.z); mx.w = fmaxf(mx.w, m.w);
            sm.x += q.x; sm.y += q.y; sm.z += q.z; sm.w += q.w;
            smax[ty][tx] = mx;
            ssum[ty][tx] = sm;
        }
        __syncthreads();
    }

    if (ty == 0) {
        const float inv = 1.0f / C;
        sm.x *= inv; sm.y *= inv; sm.z *= inv; sm.w *= inv;
        float4* pool4 = reinterpret_cast<float4*>(g_pooled);
        pool4[(b * 2 * HW) / 4 + hw4]      = mx;
        pool4[(b * 2 * HW + HW) / 4 + hw4] = sm;
    }
}

// ---------------------------------------------------------------------------
// Kernel 2: smem-tiled 7x7 conv + sigmoid + keyword bias (CROWS=8).
// Plain launch. Implicit programmatic-completion at kernel end releases mul.
// ---------------------------------------------------------------------------
__global__ void conv_kernel(const float* __restrict__ conv_w,
                            const float* __restrict__ conv_b,
                            const float* __restrict__ keyword,
                            const float* __restrict__ proj_w,
                            const float* __restrict__ proj_b) {
    __shared__ float tile[2][CTH][CTW];   // 7 KB
    __shared__ float wts[98];
    __shared__ float wsum[8];
    __shared__ float sbias;

    int b  = blockIdx.y;
    int r0 = blockIdx.x * CROWS;
    int tid = threadIdx.x;

    if (tid < 98) wts[tid] = __ldg(conv_w + tid);

    {
        float s = 0.0f;
        const float* kb = keyword + b * KD;
#pragma unroll
        for (int k = tid; k < KD; k += 256)
            s += __ldg(kb + k) * __ldg(proj_w + k);
#pragma unroll
        for (int off = 16; off > 0; off >>= 1)
            s += __shfl_down_sync(0xFFFFFFFFu, s, off);
        if ((tid & 31) == 0) wsum[tid >> 5] = s;
    }

    const float* pb = g_pooled + b * 2 * HW;
    for (int i = tid; i < 2 * CTH * CTW; i += 256) {
        int ci = i / (CTH * CTW);
        int rr = (i / CTW) % CTH;
        int cc = i % CTW;
        int hh = r0 + rr - 3;
        int ww = cc - 3;
        float v = 0.0f;
        if ((unsigned)hh < (unsigned)H && (unsigned)ww < (unsigned)W)
            v = pb[ci * HW + hh * W + ww];
        tile[ci][rr][cc] = v;
    }
    __syncthreads();

    if (tid == 0) {
        float t = 0.0f;
#pragma unroll
        for (int i = 0; i < 8; ++i) t += wsum[i];
        sbias = t + __ldg(proj_b) + __ldg(conv_b);
    }
    __syncthreads();

#pragma unroll
    for (int o = tid; o < CROWS * W; o += 256) {
        int r = o / W;
        int w = o - r * W;
        float acc = sbias;
#pragma unroll
        for (int ci = 0; ci < 2; ++ci) {
#pragma unroll
            for (int kh = 0; kh < 7; ++kh) {
#pragma unroll
                for (int kw = 0; kw < 7; ++kw) {
                    acc += tile[ci][r + kh][w + kw] * wts[ci * 49 + kh * 7 + kw];
                }
            }
        }
        g_scale[b * HW + (r0 + r) * W + w] = 1.0f / (1.0f + __expf(-acc));
    }
}

// ---------------------------------------------------------------------------
// Kernel 3: out = x * scale, PDL: the x load (conv-independent) issues
// before grid-dep-sync, overlapping conv's execution; scale read + store
// after the sync.
// ---------------------------------------------------------------------------
__global__ void mul_kernel(const float4* __restrict__ x4,
                           float4* __restrict__ out4) {
    const int CHW4 = C * HW4;
    int i = blockIdx.x * blockDim.x + threadIdx.x;
    bool active = (i < (int)(NTOT / 4));

    float4 v = make_float4(0.f, 0.f, 0.f, 0.f);
    int b = 0, hw4 = 0;
    if (active) {
        b       = i / CHW4;
        int rem = i - b * CHW4;
        hw4     = rem % HW4;
        v = __ldcs(x4 + i);               // overlaps conv
    }

#if __CUDA_ARCH__ >= 900
    cudaGridDependencySynchronize();      // wait for conv's g_scale
#endif

    if (active) {
        float4 s = reinterpret_cast<const float4*>(g_scale)[b * HW4 + hw4];
        v.x *= s.x; v.y *= s.y; v.z *= s.z; v.w *= s.w;
        __stcs(out4 + i, v);
    }
}

// ---------------------------------------------------------------------------
extern "C" void kernel_launch(void* const* d_in, const int* in_sizes, int n_in,
                              void* d_out, int out_size) {
    const float* x       = (const float*)d_in[0];
    const float* keyword = (const float*)d_in[1];
    const float* conv_w  = (const float*)d_in[2];
    const float* conv_b  = (const float*)d_in[3];
    const float* proj_w  = (const float*)d_in[4];
    const float* proj_b  = (const float*)d_in[5];
    float* out = (float*)d_out;

    // 1) pool — plain launch (untouched bandwidth-bound producer)
    {
        dim3 grid(PBLK_PER_B, B);        // 49 x 32
        pool_kernel<<<grid, PTX * PTY>>>((const float4*)x);
    }
    // 2) conv — plain launch
    {
        dim3 grid(H / CROWS, B);         // 7 x 32 = 224
        conv_kernel<<<grid, 256>>>(conv_w, conv_b, keyword, proj_w, proj_b);
    }
    // 3) mul — PDL: may start during conv; syncs on grid dependency inside
    {
        int n4 = (int)(NTOT / 4);
        dim3 grid((n4 + 255) / 256);
        const float4* xa = (const float4*)x;
        float4* oa = (float4*)out;
        void* args[] = { (void*)&xa, (void*)&oa };

        cudaLaunchAttribute attr[1];
        attr[0].id = cudaLaunchAttributeProgrammaticStreamSerialization;
        attr[0].val.programmaticStreamSerializationAllowed = 1;
        cudaLaunchConfig_t cfg{};
        cfg.gridDim  = grid;
        cfg.blockDim = dim3(256);
        cfg.dynamicSmemBytes = 0;
        cfg.stream   = 0;
        cfg.attrs    = attr;
        cfg.numAttrs = 1;
        cudaLaunchKernelExC(&cfg, (void*)mul_kernel, args);
    }
}